// round 12
// baseline (speedup 1.0000x reference)
#include <cuda_runtime.h>
#include <cuda_fp16.h>
#include <math.h>

#define NN 80000
#define NE 1280000
#define NG 512
#define FF 64
#define KP 200   // padded k-stride (halves) for fp16 tiles

// ---------------- scratch (device globals, no allocation) ----------------
// Invariant: g_cnt, g_cursor, g_pooled are ZERO on entry to kernel_launch
// (zero-initialized at module load; each consumer restores zeros after use).
__device__ __align__(16) float g_hA[NN*FF];
__device__ __align__(16) float g_hB[NN*FF];
__device__ __align__(16) float g_x4[NN*4];
__device__ __align__(16) float g_B0[NN*4];
__device__ __align__(16) float g_B1[NN*4];
__device__ __align__(16) float g_pooled[NG*FF];
__device__ __align__(16) __half g_Wt16[3*64*KP];   // per-layer [n=64][k=192] fp16, padded
__device__ int   g_cnt[NN];
__device__ int   g_cursor[NN];
__device__ int   g_off[NN+1];
__device__ int   g_bsum[320];
__device__ __align__(16) int2 g_edge[NE];          // {src, u bits}

// ---------------- helpers ----------------
__device__ __forceinline__ void red_add_v4(float* p, float4 v) {
    asm volatile("red.global.add.v4.f32 [%0], {%1,%2,%3,%4};"
                 :: "l"(p), "f"(v.x), "f"(v.y), "f"(v.z), "f"(v.w) : "memory");
}
__device__ __forceinline__ float elu1(float v) { return v > 0.0f ? v : expm1f(v); }

__device__ __forceinline__ void mma16816(float* c, unsigned a0, unsigned a1,
                                         unsigned a2, unsigned a3,
                                         unsigned b0, unsigned b1) {
    asm volatile(
        "mma.sync.aligned.m16n8k16.row.col.f32.f16.f16.f32 "
        "{%0,%1,%2,%3}, {%4,%5,%6,%7}, {%8,%9}, {%0,%1,%2,%3};\n"
        : "+f"(c[0]), "+f"(c[1]), "+f"(c[2]), "+f"(c[3])
        : "r"(a0), "r"(a1), "r"(a2), "r"(a3), "r"(b0), "r"(b1));
}

// ---------------- hist (+ pack x): g_cnt assumed zero on entry ------------
__global__ void k_hist(const int* __restrict__ dst, const float* __restrict__ x) {
    int e = blockIdx.x * blockDim.x + threadIdx.x;   // exactly NE threads
    if (e < NN) {
        float4 v; v.x = x[e*3+0]; v.y = x[e*3+1]; v.z = x[e*3+2]; v.w = 0.f;
        ((float4*)g_x4)[e] = v;
    }
    atomicAdd(&g_cnt[dst[e]], 1);
}

__global__ void k_scan1() {
    __shared__ int wsum[8];
    int b = blockIdx.x, tid = threadIdx.x, lane = tid & 31, w = tid >> 5;
    int i = b * 256 + tid;
    int v = (i < NN) ? g_cnt[i] : 0;
    if (i < NN) g_cnt[i] = 0;        // restore zero-at-entry invariant
    int inc = v;
    #pragma unroll
    for (int o = 1; o < 32; o <<= 1) {
        int nv = __shfl_up_sync(0xffffffffu, inc, o);
        if (lane >= o) inc += nv;
    }
    if (lane == 31) wsum[w] = inc;
    __syncthreads();
    if (w == 0 && lane < 8) {
        int x = wsum[lane];
        int xi = x;
        #pragma unroll
        for (int o = 1; o < 8; o <<= 1) {
            int nv = __shfl_up_sync(0xffu, xi, o, 8);
            if (lane >= o) xi += nv;
        }
        wsum[lane] = xi - x;
        if (lane == 7) g_bsum[b] = xi;
    }
    __syncthreads();
    if (i < NN) g_off[i] = wsum[w] + (inc - v);
}

#define NB_SCAN 313
// scan3: each block computes its own exclusive block-offset from g_bsum
__global__ void k_scan3() {
    __shared__ int red[8];
    __shared__ int s_boff;
    int b = blockIdx.x, tid = threadIdx.x, lane = tid & 31, w = tid >> 5;
    // partial sum of g_bsum[j] for j < b, j = tid, tid+256
    int p = 0;
    if (tid < b)       p += g_bsum[tid];
    if (tid + 256 < b) p += g_bsum[tid + 256];
    #pragma unroll
    for (int o = 16; o > 0; o >>= 1) p += __shfl_down_sync(0xffffffffu, p, o);
    if (lane == 0) red[w] = p;
    __syncthreads();
    if (tid == 0) {
        int s = red[0];
        #pragma unroll
        for (int k = 1; k < 8; ++k) s += red[k];
        s_boff = s;
    }
    __syncthreads();
    int i = b * 256 + tid;
    if (i < NN) g_off[i] += s_boff;
    if (b == 0 && tid == 0) g_off[NN] = NE;
}

__global__ void k_fill(const int* __restrict__ src, const int* __restrict__ dst,
                       const float* __restrict__ u) {
    int e = blockIdx.x * blockDim.x + threadIdx.x;
    int d = dst[e];
    int pos = g_off[d] + atomicAdd(&g_cursor[d], 1);
    g_edge[pos] = make_int2(src[e], __float_as_int(u[e]));
}

// ---------------- weight convert: Wt16[l][n][k] = fp16(Wcat[k][n]) ---------
__global__ void k_cvtw(const float* __restrict__ Wa, const float* __restrict__ ra,
                       const float* __restrict__ Wb, const float* __restrict__ rb,
                       const float* __restrict__ Wc, const float* __restrict__ rc) {
    int t = blockIdx.x * blockDim.x + threadIdx.x;   // 3*64*192 threads
    if (t >= 3*64*192) return;
    int layer = t / (64*192);
    int r = t % (64*192);
    int n = r / 192, k = r % 192;
    const float* W    = (layer == 0) ? Wa : (layer == 1) ? Wb : Wc;
    const float* root = (layer == 0) ? ra : (layer == 1) ? rb : rc;
    float v = (k < 128) ? W[k*64 + n] : root[(k-128)*64 + n];
    g_Wt16[layer*64*KP + n*KP + k] = __float2half_rn(v);
}

// ---------------- layer 1: aggregate raw x (3-dim) then transform ----------
__global__ void k_gather3() {
    int n = blockIdx.x * blockDim.x + threadIdx.x;
    if (n >= NN) return;
    g_cursor[n] = 0;                 // restore zero-at-entry invariant
    int beg = g_off[n], end = g_off[n+1];
    float sa0=0,sa1=0,sa2=0, ta0=0,ta1=0,ta2=0;
    float sb0=0,sb1=0,sb2=0, tb0=0,tb1=0,tb2=0;
    const float4* X4 = (const float4*)g_x4;
    int e = beg;
    for (; e + 1 < end; e += 2) {
        int2 eA = __ldg(&g_edge[e]);
        int2 eB = __ldg(&g_edge[e+1]);
        float uA = __int_as_float(eA.y);
        float uB = __int_as_float(eB.y);
        float4 xa = __ldg(&X4[eA.x]);
        float4 xb = __ldg(&X4[eB.x]);
        sa0 += xa.x; sa1 += xa.y; sa2 += xa.z;
        ta0 += uA*xa.x; ta1 += uA*xa.y; ta2 += uA*xa.z;
        sb0 += xb.x; sb1 += xb.y; sb2 += xb.z;
        tb0 += uB*xb.x; tb1 += uB*xb.y; tb2 += uB*xb.z;
    }
    if (e < end) {
        int2 eA = __ldg(&g_edge[e]);
        float uA = __int_as_float(eA.y);
        float4 xa = __ldg(&X4[eA.x]);
        sa0 += xa.x; sa1 += xa.y; sa2 += xa.z;
        ta0 += uA*xa.x; ta1 += uA*xa.y; ta2 += uA*xa.z;
    }
    float t0 = ta0+tb0, t1 = ta1+tb1, t2 = ta2+tb2;
    g_B0[n*4+0] = (sa0+sb0) - t0; g_B0[n*4+1] = (sa1+sb1) - t1; g_B0[n*4+2] = (sa2+sb2) - t2;
    g_B1[n*4+0] = t0; g_B1[n*4+1] = t1; g_B1[n*4+2] = t2;
}

__global__ void k_layer1(const float* __restrict__ x, const float* __restrict__ W,
                         const float* __restrict__ root, const float* __restrict__ b) {
    int t = blockIdx.x * blockDim.x + threadIdx.x;
    int n = t >> 6, f = t & 63;
    float agg = g_B0[n*4+0]*__ldg(&W[f])      + g_B0[n*4+1]*__ldg(&W[64+f])  + g_B0[n*4+2]*__ldg(&W[128+f])
              + g_B1[n*4+0]*__ldg(&W[192+f])  + g_B1[n*4+1]*__ldg(&W[256+f]) + g_B1[n*4+2]*__ldg(&W[320+f]);
    int dg = g_off[n+1] - g_off[n];
    float inv = 1.0f / (dg < 1 ? 1 : dg);
    float yr = x[n*3+0]*__ldg(&root[f]) + x[n*3+1]*__ldg(&root[64+f]) + x[n*3+2]*__ldg(&root[128+f]);
    g_hA[t] = elu1(agg*inv + yr + __ldg(&b[f]));
}

// ---------------- fused gather + tensor-core GEMM layer (layers 2-4) -------
// F = [A0*inv | A1*inv | H] (64 x 192, fp16 in smem, row pad KP=200)
// h_out = elu( F @ Wt^T + b ), Wt fp16 [n=64][k=192] in global.
__global__ __launch_bounds__(256) void k_glayer(int insel, int outsel, int layer,
                                                const float* __restrict__ bias) {
    __shared__ __half sA[64 * KP];                  // 25600 B
    const float* hin  = insel  ? g_hB : g_hA;
    float*       hout = outsel ? g_hB : g_hA;
    const int nb = blockIdx.x * 64;
    const int tid = threadIdx.x;
    const int lane = tid & 31;
    const int warp = tid >> 5;
    const int j = lane & 15;
    const int half = lane >> 4;

    const float4* H4 = (const float4*)hin;

    // stage H rows (fp32 -> fp16) into sA[.][128..191]
    for (int i = tid; i < 64*16; i += 256) {
        int r = i >> 4, jj = i & 15;
        float4 v = H4[(long)(nb + r)*16 + jj];
        __half2 h0 = __floats2half2_rn(v.x, v.y);
        __half2 h1 = __floats2half2_rn(v.z, v.w);
        uint2 pk; pk.x = *(unsigned*)&h0; pk.y = *(unsigned*)&h1;
        *(uint2*)&sA[r*KP + 128 + 4*jj] = pk;
    }

    // gather: 1 warp per node, 2 edges in flight per half-warp
    for (int q = 0; q < 8; ++q) {
        int n = nb + warp*8 + q;
        int beg = g_off[n], end = g_off[n+1];
        int d = end - beg;
        float inv = 1.0f / (d < 1 ? 1 : d);
        int mid = beg + ((d + 1) >> 1);
        int e0 = half ? mid : beg;
        int e1 = half ? end : mid;
        float4 sa = make_float4(0.f,0.f,0.f,0.f), ta = make_float4(0.f,0.f,0.f,0.f);
        float4 sb = make_float4(0.f,0.f,0.f,0.f), tb = make_float4(0.f,0.f,0.f,0.f);
        int e = e0;
        for (; e + 1 < e1; e += 2) {
            int2 eA = __ldg(&g_edge[e]);
            int2 eB = __ldg(&g_edge[e+1]);
            float uA = __int_as_float(eA.y);
            float uB = __int_as_float(eB.y);
            float4 vA = H4[(long)eA.x*16 + j];
            float4 vB = H4[(long)eB.x*16 + j];
            sa.x += vA.x; sa.y += vA.y; sa.z += vA.z; sa.w += vA.w;
            ta.x += uA*vA.x; ta.y += uA*vA.y; ta.z += uA*vA.z; ta.w += uA*vA.w;
            sb.x += vB.x; sb.y += vB.y; sb.z += vB.z; sb.w += vB.w;
            tb.x += uB*vB.x; tb.y += uB*vB.y; tb.z += uB*vB.z; tb.w += uB*vB.w;
        }
        if (e < e1) {
            int2 eA = __ldg(&g_edge[e]);
            float uA = __int_as_float(eA.y);
            float4 vA = H4[(long)eA.x*16 + j];
            sa.x += vA.x; sa.y += vA.y; sa.z += vA.z; sa.w += vA.w;
            ta.x += uA*vA.x; ta.y += uA*vA.y; ta.z += uA*vA.z; ta.w += uA*vA.w;
        }
        float4 sum, t;
        sum.x = sa.x + sb.x; sum.y = sa.y + sb.y; sum.z = sa.z + sb.z; sum.w = sa.w + sb.w;
        t.x = ta.x + tb.x; t.y = ta.y + tb.y; t.z = ta.z + tb.z; t.w = ta.w + tb.w;
        sum.x += __shfl_xor_sync(0xffffffffu, sum.x, 16);
        sum.y += __shfl_xor_sync(0xffffffffu, sum.y, 16);
        sum.z += __shfl_xor_sync(0xffffffffu, sum.z, 16);
        sum.w += __shfl_xor_sync(0xffffffffu, sum.w, 16);
        t.x += __shfl_xor_sync(0xffffffffu, t.x, 16);
        t.y += __shfl_xor_sync(0xffffffffu, t.y, 16);
        t.z += __shfl_xor_sync(0xffffffffu, t.z, 16);
        t.w += __shfl_xor_sync(0xffffffffu, t.w, 16);
        int r = warp*8 + q;
        float4 o;
        if (half == 0) {   // A0 = (sum - t) * inv, k = [0,64)
            o.x = (sum.x - t.x) * inv; o.y = (sum.y - t.y) * inv;
            o.z = (sum.z - t.z) * inv; o.w = (sum.w - t.w) * inv;
        } else {           // A1 = t * inv, k = [64,128)
            o.x = t.x * inv; o.y = t.y * inv; o.z = t.z * inv; o.w = t.w * inv;
        }
        __half2 h0 = __floats2half2_rn(o.x, o.y);
        __half2 h1 = __floats2half2_rn(o.z, o.w);
        uint2 pk; pk.x = *(unsigned*)&h0; pk.y = *(unsigned*)&h1;
        *(uint2*)&sA[r*KP + half*64 + 4*j] = pk;
    }
    __syncthreads();

    // tensor-core GEMM: warp -> m16 x n32 tile; 12 k-chunks of 16
    const int g  = lane >> 2;       // group id 0..7
    const int tg = lane & 3;        // thread-in-group 0..3
    const int mtile = warp & 3;     // rows 16*mtile
    const int nhalf = warp >> 2;    // cols 32*nhalf
    const int mb = mtile * 16;

    const __half* Wt = g_Wt16 + layer*64*KP;

    float acc[4][4];
    #pragma unroll
    for (int nt = 0; nt < 4; ++nt)
        #pragma unroll
        for (int c = 0; c < 4; ++c) acc[nt][c] = 0.f;

    #pragma unroll
    for (int kc = 0; kc < 12; ++kc) {
        int kb = kc * 16;
        const __half* pa = &sA[(mb + g)*KP + kb + 2*tg];
        unsigned a0 = *(const unsigned*)(pa);
        unsigned a1 = *(const unsigned*)(pa + 8*KP);
        unsigned a2 = *(const unsigned*)(pa + 8);
        unsigned a3 = *(const unsigned*)(pa + 8*KP + 8);
        #pragma unroll
        for (int nt = 0; nt < 4; ++nt) {
            int ncol = nhalf*32 + nt*8 + g;
            const __half* pb = &Wt[ncol*KP + kb + 2*tg];
            unsigned b0 = __ldg((const unsigned*)(pb));
            unsigned b1 = __ldg((const unsigned*)(pb + 8));
            mma16816(acc[nt], a0, a1, a2, a3, b0, b1);
        }
    }

    // epilogue: bias + elu, write fp32 h
    #pragma unroll
    for (int nt = 0; nt < 4; ++nt) {
        int col = nhalf*32 + nt*8 + 2*tg;
        float2 bv = *(const float2*)&bias[col];
        int m0 = nb + mb + g;
        float2 o0, o1;
        o0.x = elu1(acc[nt][0] + bv.x);
        o0.y = elu1(acc[nt][1] + bv.y);
        o1.x = elu1(acc[nt][2] + bv.x);
        o1.y = elu1(acc[nt][3] + bv.y);
        *(float2*)&hout[(long)m0*64 + col]       = o0;
        *(float2*)&hout[(long)(m0+8)*64 + col]   = o1;
    }
}

// ---------------- pooling ----------------
#define POOL_CHUNK 64
#define POOL_NCHUNK ((NN + POOL_CHUNK - 1) / POOL_CHUNK)   // 1250
__global__ void k_pool(const int* __restrict__ batch) {
    int t = blockIdx.x * blockDim.x + threadIdx.x;
    int j = t & 15;
    int c = t >> 4;
    if (c >= POOL_NCHUNK) return;
    int n0 = c * POOL_CHUNK;
    int n1 = n0 + POOL_CHUNK; if (n1 > NN) n1 = NN;
    const float4* h4 = (const float4*)g_hB;
    float4 acc = make_float4(0.f,0.f,0.f,0.f);
    int g = batch[n0];
    for (int n = n0; n < n1; ++n) {
        int gg = batch[n];
        if (gg != g) {
            red_add_v4(&g_pooled[g*64 + j*4], acc);
            acc = make_float4(0.f,0.f,0.f,0.f);
            g = gg;
        }
        float4 v = h4[(long)n*16 + j];
        acc.x += v.x; acc.y += v.y; acc.z += v.z; acc.w += v.w;
    }
    red_add_v4(&g_pooled[g*64 + j*4], acc);
}

// ---------------- head ----------------
__global__ void k_head(const int* __restrict__ batch, const float* __restrict__ fcw,
                       const float* __restrict__ fcb, float* __restrict__ out) {
    int g = blockIdx.x * blockDim.x + threadIdx.x;
    if (g >= NG) return;
    int lo, hi, c0, c1;
    lo = 0; hi = NN;
    while (lo < hi) { int mid = (lo + hi) >> 1; if (batch[mid] < g) lo = mid + 1; else hi = mid; }
    c0 = lo;
    lo = 0; hi = NN;
    while (lo < hi) { int mid = (lo + hi) >> 1; if (batch[mid] < g + 1) lo = mid + 1; else hi = mid; }
    c1 = lo;
    float cnt = (float)(c1 - c0);
    float inv = 1.0f / (cnt < 1.0f ? 1.0f : cnt);

    float logit[6];
    #pragma unroll
    for (int cc = 0; cc < 6; ++cc) logit[cc] = fcb[cc];
    for (int k = 0; k < 64; ++k) {
        float p = g_pooled[g*64 + k] * inv;
        g_pooled[g*64 + k] = 0.0f;   // restore zero-at-entry invariant
        #pragma unroll
        for (int cc = 0; cc < 6; ++cc) logit[cc] += p * fcw[k*6 + cc];
    }
    float m = logit[0];
    #pragma unroll
    for (int cc = 1; cc < 6; ++cc) m = fmaxf(m, logit[cc]);
    float s = 0.f;
    #pragma unroll
    for (int cc = 0; cc < 6; ++cc) s += expf(logit[cc] - m);
    float l = logf(s);
    #pragma unroll
    for (int cc = 0; cc < 6; ++cc) out[g*6 + cc] = logit[cc] - m - l;
}

// ---------------- launch ----------------
extern "C" void kernel_launch(void* const* d_in, const int* in_sizes, int n_in,
                              void* d_out, int out_size) {
    const float* x      = (const float*)d_in[0];
    const float* pseudo = (const float*)d_in[1];
    const int*   ei     = (const int*)d_in[2];
    const int*   batch  = (const int*)d_in[3];
    const float* W1 = (const float*)d_in[4];
    const float* r1 = (const float*)d_in[5];
    const float* b1 = (const float*)d_in[6];
    const float* W2 = (const float*)d_in[7];
    const float* r2 = (const float*)d_in[8];
    const float* b2 = (const float*)d_in[9];
    const float* W3 = (const float*)d_in[10];
    const float* r3 = (const float*)d_in[11];
    const float* b3 = (const float*)d_in[12];
    const float* W4 = (const float*)d_in[13];
    const float* r4 = (const float*)d_in[14];
    const float* b4 = (const float*)d_in[15];
    const float* fcw = (const float*)d_in[16];
    const float* fcb = (const float*)d_in[17];
    float* out = (float*)d_out;

    const int* src = ei;
    const int* dst = ei + NE;

    // CSR build (g_cnt/g_cursor/g_pooled are zero on entry — see invariant)
    k_hist<<<NE/256, 256>>>(dst, x);
    k_scan1<<<NB_SCAN, 256>>>();
    k_scan3<<<NB_SCAN, 256>>>();
    k_fill<<<NE/256, 256>>>(src, dst, pseudo);
    k_cvtw<<<(3*64*192 + 255)/256, 256>>>(W2, r2, W3, r3, W4, r4);

    // layer 1 (Fin=3)
    k_gather3<<<(NN + 255)/256, 256>>>();
    k_layer1<<<(NN*FF)/256, 256>>>(x, W1, r1, b1);           // -> hA

    // layers 2-4: fused gather + tensor-core GEMM
    k_glayer<<<NN/64, 256>>>(0, 1, 0, b2);                   // hA -> hB
    k_glayer<<<NN/64, 256>>>(1, 0, 1, b3);                   // hB -> hA
    k_glayer<<<NN/64, 256>>>(0, 1, 2, b4);                   // hA -> hB

    // pooling + head
    k_pool<<<(POOL_NCHUNK*16 + 255)/256, 256>>>(batch);
    k_head<<<(NG + 255)/256, 256>>>(batch, fcw, fcb, out);
}